// round 4
// baseline (speedup 1.0000x reference)
#include <cuda_runtime.h>
#include <cstdint>

// ---------------- problem constants ----------------
constexpr int  B_    = 16;
constexpr int  N_    = 1024;
constexpr int  CIN   = 768;
constexpr int  H_    = 8;
constexpr int  KQ_   = 256;
constexpr int  VD_   = 512;
constexpr long MTOK  = 16384;
constexpr long QKVC  = 8192;
constexpr long NHV   = 4096;
constexpr int  DOUT  = 512;
constexpr float SCALE_ = 0.04419417382415922f;     // 512^-0.5
constexpr float EPS_   = 1e-5f;

// ---------------- scratch (device globals) ----------------
__device__ float g_qkv [MTOK * QKVC];                      // 512 MB
__device__ float g_attn[(long)B_ * H_ * N_ * N_];          // 536 MB
__device__ float g_ao  [MTOK * NHV];                       // 268 MB
__device__ float g_vt  [(long)B_ * H_ * VD_ * N_];         // 256 MB
__device__ float g_xr  [MTOK * CIN];                       // 48 MB  (tf32-rounded x)
__device__ float g_wr  [QKVC * CIN];                       // 25 MB  (tf32-rounded qkv_w)
__device__ float g_pwr [(long)DOUT * NHV];                 // 8 MB   (tf32-rounded proj_w)
__device__ float g_qs[QKVC], g_qh[QKVC];
__device__ float g_ps[DOUT], g_ph[DOUT];

// ---------------- helpers ----------------
__device__ __forceinline__ float to_tf32(float x) {
    uint32_t u;
    asm("cvt.rna.tf32.f32 %0, %1;" : "=r"(u) : "f"(x));
    return __uint_as_float(u);
}
__device__ __forceinline__ void cp16(uint32_t s, const float* g) {
    asm volatile("cp.async.cg.shared.global [%0], [%1], 16;"
                 :: "r"(s), "l"(__cvta_generic_to_global(g)));
}
__device__ __forceinline__ uint32_t smem_u32(const void* p) {
    uint32_t a;
    asm("{ .reg .u64 t; cvta.to.shared.u64 t, %1; cvt.u32.u64 %0, t; }" : "=r"(a) : "l"(p));
    return a;
}
__device__ __forceinline__ void mma_tf32(float* c, const uint32_t* a, const uint32_t* b) {
    asm volatile(
        "mma.sync.aligned.m16n8k8.row.col.f32.tf32.tf32.f32 "
        "{%0,%1,%2,%3}, {%4,%5,%6,%7}, {%8,%9}, {%0,%1,%2,%3};"
        : "+f"(c[0]), "+f"(c[1]), "+f"(c[2]), "+f"(c[3])
        : "r"(a[0]), "r"(a[1]), "r"(a[2]), "r"(a[3]), "r"(b[0]), "r"(b[1]));
}

// ---------------- mma.sync tf32 GEMM: tile 128x128x32, 3-stage pipeline ---------------
// A: [M][K] K-contig (tf32-rounded). B: [N][K] K-contig (tf32-rounded).
// MODE 0: round(BN)   1: alpha*acc + bias   2: round(clamp(-1,1))   3: BN (no round)
constexpr int LDT = 36;                 // padded smem row (floats) -> conflict-free frags
constexpr int CH  = 128 * LDT;          // floats per tile buffer (4608)
constexpr int NSTAGE = 3;
constexpr int SMEM_BYTES = 2 * NSTAGE * CH * 4;  // 110592 B

template<int MODE>
__global__ __launch_bounds__(256)
void mma_gemm_kernel(const float* __restrict__ Aall, long lda, long aos, long ais,
                     const float* __restrict__ Ball, long ldb, long bos, long bis,
                     float* __restrict__ Call, long ldc, long cosz, long cis,
                     int K, int zdiv,
                     const float* __restrict__ p0, const float* __restrict__ p1,
                     float alpha, long bias_is, long ldbias)
{
    extern __shared__ float sm[];       // [A0][A1][A2][B0][B1][B2]
    const uint32_t sbase = smem_u32(sm);

    const int tid = threadIdx.x;
    const int wid = tid >> 5, lane = tid & 31;
    const int wm = wid & 1, wn = wid >> 1;          // 2 x 4 warp grid
    const int rg = lane >> 2, lg = lane & 3;

    const int z  = blockIdx.z;
    const int zo = z / zdiv, zi = z - zo * zdiv;
    const float* A  = Aall + (long)zo * aos + (long)zi * ais;
    const float* Bp = Ball + (long)zo * bos + (long)zi * bis;
    float*       C  = Call + (long)zo * cosz + (long)zi * cis;
    const long m0 = (long)blockIdx.y * 128;
    const long n0 = (long)blockIdx.x * 128;

    float acc[4][4][4];
#pragma unroll
    for (int i = 0; i < 4; i++)
#pragma unroll
        for (int j = 0; j < 4; j++)
#pragma unroll
            for (int q = 0; q < 4; q++) acc[i][j][q] = 0.f;

    auto load_tile = [&](const float* src, long ld, int kc, int bufFloatOff) {
        const float* s = src + (long)kc * 32;
#pragma unroll
        for (int i = 0; i < 4; i++) {
            int idx = tid + i * 256;             // 0..1023
            int r = idx >> 3, c = idx & 7;       // row 0..127, float4 col 0..7
            cp16(sbase + (uint32_t)(r * LDT + c * 4) * 4u + (uint32_t)bufFloatOff * 4u,
                 s + (long)r * ld + c * 4);
        }
    };

    const float* Abase = A + m0 * lda;
    const float* Bbase = Bp + n0 * ldb;

    const int nch = K >> 5;       // >= 8 for all our GEMMs
    load_tile(Abase, lda, 0, 0);
    load_tile(Bbase, ldb, 0, NSTAGE * CH);
    asm volatile("cp.async.commit_group;");
    load_tile(Abase, lda, 1, CH);
    load_tile(Bbase, ldb, 1, NSTAGE * CH + CH);
    asm volatile("cp.async.commit_group;");

    int st = 0;                    // stage of chunk kc
    for (int kc = 0; kc < nch; kc++) {
        if (kc + 1 < nch) asm volatile("cp.async.wait_group 1;");
        else              asm volatile("cp.async.wait_group 0;");
        __syncthreads();

        if (kc + 2 < nch) {
            int st2 = st + 2; if (st2 >= NSTAGE) st2 -= NSTAGE;
            load_tile(Abase, lda, kc + 2, st2 * CH);
            load_tile(Bbase, ldb, kc + 2, NSTAGE * CH + st2 * CH);
            asm volatile("cp.async.commit_group;");
        }

        const float* as = sm + st * CH + (wm * 64 + rg) * LDT + lg;
        const float* bs = sm + NSTAGE * CH + st * CH + (wn * 32 + rg) * LDT + lg;
#pragma unroll
        for (int ks = 0; ks < 4; ks++) {
            uint32_t a[4][4], b[4][2];
#pragma unroll
            for (int i = 0; i < 4; i++) {
                const float* ap = as + i * (16 * LDT) + ks * 8;
                a[i][0] = __float_as_uint(ap[0]);
                a[i][1] = __float_as_uint(ap[8 * LDT]);
                a[i][2] = __float_as_uint(ap[4]);
                a[i][3] = __float_as_uint(ap[8 * LDT + 4]);
            }
#pragma unroll
            for (int j = 0; j < 4; j++) {
                const float* bp = bs + j * (8 * LDT) + ks * 8;
                b[j][0] = __float_as_uint(bp[0]);
                b[j][1] = __float_as_uint(bp[4]);
            }
#pragma unroll
            for (int i = 0; i < 4; i++)
#pragma unroll
                for (int j = 0; j < 4; j++)
                    mma_tf32(acc[i][j], a[i], b[j]);
        }
        st++; if (st >= NSTAGE) st = 0;
    }

    // -------- epilogue --------
    const long cr0 = m0 + wm * 64 + rg;
    const long cn0 = n0 + wn * 32 + 2 * lg;
#pragma unroll
    for (int i = 0; i < 4; i++) {
        const long r0 = cr0 + i * 16, r1 = r0 + 8;
#pragma unroll
        for (int j = 0; j < 4; j++) {
            const long cc = cn0 + j * 8;
            float v0 = acc[i][j][0], v1 = acc[i][j][1];
            float v2 = acc[i][j][2], v3 = acc[i][j][3];
            if (MODE == 0 || MODE == 3) {
                const float s0 = p0[cc], s1 = p0[cc + 1];
                const float h0 = p1[cc], h1 = p1[cc + 1];
                v0 = fmaf(v0, s0, h0); v1 = fmaf(v1, s1, h1);
                v2 = fmaf(v2, s0, h0); v3 = fmaf(v3, s1, h1);
                if (MODE == 0) { v0 = to_tf32(v0); v1 = to_tf32(v1); v2 = to_tf32(v2); v3 = to_tf32(v3); }
            } else if (MODE == 1) {
                const float* bias = p0 + (long)zi * bias_is;
                const float2 b0 = *(const float2*)(bias + r0 * ldbias + cc);
                const float2 b1 = *(const float2*)(bias + r1 * ldbias + cc);
                v0 = fmaf(v0, alpha, b0.x); v1 = fmaf(v1, alpha, b0.y);
                v2 = fmaf(v2, alpha, b1.x); v3 = fmaf(v3, alpha, b1.y);
            } else {
                v0 = to_tf32(fminf(fmaxf(v0, -1.f), 1.f));
                v1 = to_tf32(fminf(fmaxf(v1, -1.f), 1.f));
                v2 = to_tf32(fminf(fmaxf(v2, -1.f), 1.f));
                v3 = to_tf32(fminf(fmaxf(v3, -1.f), 1.f));
            }
            *(float2*)(C + r0 * ldc + cc) = make_float2(v0, v1);
            *(float2*)(C + r1 * ldc + cc) = make_float2(v2, v3);
        }
    }
}

// ---------------- small kernels ----------------
__global__ void bn_prep_kernel(const float* __restrict__ g, const float* __restrict__ b,
                               const float* __restrict__ mu, const float* __restrict__ var,
                               float* __restrict__ sc, float* __restrict__ sh, int n) {
    int i = blockIdx.x * blockDim.x + threadIdx.x;
    if (i < n) {
        float s = g[i] * rsqrtf(var[i] + EPS_);
        sc[i] = s;
        sh[i] = b[i] - mu[i] * s;
    }
}

__global__ void round_copy_kernel(const float* __restrict__ in, float* __restrict__ out, long n) {
    long i = ((long)blockIdx.x * blockDim.x + threadIdx.x) * 4;
    if (i < n) {
        float4 v = *(const float4*)(in + i);
        v.x = to_tf32(v.x); v.y = to_tf32(v.y); v.z = to_tf32(v.z); v.w = to_tf32(v.w);
        *(float4*)(out + i) = v;
    }
}

// V transpose: qkv[b,n][h*1024+512+d] -> vt[(b*8+h)*512+d][n]
__global__ void transpose_v_kernel(const float* __restrict__ qkv, float* __restrict__ vt) {
    __shared__ float t[32][33];
    const int z = blockIdx.z, b = z >> 3, h = z & 7;
    const long n0 = (long)blockIdx.x * 32, d0 = (long)blockIdx.y * 32;
    const int tx = threadIdx.x, ty = threadIdx.y;
    const float* src = qkv + (long)b * N_ * QKVC + (long)h * 1024 + 512;
#pragma unroll
    for (int i = 0; i < 32; i += 8)
        t[ty + i][tx] = src[(n0 + ty + i) * QKVC + d0 + tx];
    __syncthreads();
    float* dst = vt + ((long)z * VD_ + d0) * N_ + n0;
#pragma unroll
    for (int i = 0; i < 32; i += 8)
        dst[(ty + i) * (long)N_ + tx] = t[tx][ty + i];
}

// rowwise softmax over 1024, outputs tf32-rounded (fed into mma)
__global__ void softmax1024_kernel(float* __restrict__ attn) {
    float* p = attn + (long)blockIdx.x * 1024;
    const int t = threadIdx.x;
    float4 a = ((const float4*)p)[t];
    float4 b = ((const float4*)p)[t + 128];

    float m = fmaxf(fmaxf(fmaxf(a.x, a.y), fmaxf(a.z, a.w)),
                    fmaxf(fmaxf(b.x, b.y), fmaxf(b.z, b.w)));
#pragma unroll
    for (int o = 16; o > 0; o >>= 1) m = fmaxf(m, __shfl_xor_sync(0xffffffffu, m, o));
    __shared__ float sm_[4], ss[4];
    if ((t & 31) == 0) sm_[t >> 5] = m;
    __syncthreads();
    m = fmaxf(fmaxf(sm_[0], sm_[1]), fmaxf(sm_[2], sm_[3]));

    a.x = __expf(a.x - m); a.y = __expf(a.y - m); a.z = __expf(a.z - m); a.w = __expf(a.w - m);
    b.x = __expf(b.x - m); b.y = __expf(b.y - m); b.z = __expf(b.z - m); b.w = __expf(b.w - m);

    float s = a.x + a.y + a.z + a.w + b.x + b.y + b.z + b.w;
#pragma unroll
    for (int o = 16; o > 0; o >>= 1) s += __shfl_xor_sync(0xffffffffu, s, o);
    if ((t & 31) == 0) ss[t >> 5] = s;
    __syncthreads();
    s = ss[0] + ss[1] + ss[2] + ss[3];
    const float inv = 1.0f / s;

    a.x = to_tf32(a.x * inv); a.y = to_tf32(a.y * inv);
    a.z = to_tf32(a.z * inv); a.w = to_tf32(a.w * inv);
    b.x = to_tf32(b.x * inv); b.y = to_tf32(b.y * inv);
    b.z = to_tf32(b.z * inv); b.w = to_tf32(b.w * inv);
    ((float4*)p)[t] = a;
    ((float4*)p)[t + 128] = b;
}

// ---------------- launch ----------------
extern "C" void kernel_launch(void* const* d_in, const int* in_sizes, int n_in,
                              void* d_out, int out_size) {
    const float* x          = (const float*)d_in[0];
    const float* qkv_w      = (const float*)d_in[1];
    const float* qkv_gamma  = (const float*)d_in[2];
    const float* qkv_beta   = (const float*)d_in[3];
    const float* qkv_mean   = (const float*)d_in[4];
    const float* qkv_var    = (const float*)d_in[5];
    const float* pos_bias   = (const float*)d_in[6];
    const float* proj_w     = (const float*)d_in[7];
    const float* proj_gamma = (const float*)d_in[8];
    const float* proj_beta  = (const float*)d_in[9];
    const float* proj_mean  = (const float*)d_in[10];
    const float* proj_var   = (const float*)d_in[11];
    float* out = (float*)d_out;

    float *qkv, *attn, *ao, *vt, *xr, *wr, *pwr, *qs, *qh, *ps, *ph;
    cudaGetSymbolAddress((void**)&qkv,  g_qkv);
    cudaGetSymbolAddress((void**)&attn, g_attn);
    cudaGetSymbolAddress((void**)&ao,   g_ao);
    cudaGetSymbolAddress((void**)&vt,   g_vt);
    cudaGetSymbolAddress((void**)&xr,   g_xr);
    cudaGetSymbolAddress((void**)&wr,   g_wr);
    cudaGetSymbolAddress((void**)&pwr,  g_pwr);
    cudaGetSymbolAddress((void**)&qs,   g_qs);
    cudaGetSymbolAddress((void**)&qh,   g_qh);
    cudaGetSymbolAddress((void**)&ps,   g_ps);
    cudaGetSymbolAddress((void**)&ph,   g_ph);

    cudaFuncSetAttribute(mma_gemm_kernel<0>, cudaFuncAttributeMaxDynamicSharedMemorySize, SMEM_BYTES);
    cudaFuncSetAttribute(mma_gemm_kernel<1>, cudaFuncAttributeMaxDynamicSharedMemorySize, SMEM_BYTES);
    cudaFuncSetAttribute(mma_gemm_kernel<2>, cudaFuncAttributeMaxDynamicSharedMemorySize, SMEM_BYTES);
    cudaFuncSetAttribute(mma_gemm_kernel<3>, cudaFuncAttributeMaxDynamicSharedMemorySize, SMEM_BYTES);

    // tf32-round inputs that feed MMAs (first, so launch #6 = QKV GEMM for ncu -s 5 -c 1)
    round_copy_kernel<<<(int)((MTOK * CIN / 4 + 255) / 256), 256>>>(x, xr, MTOK * CIN);
    round_copy_kernel<<<(int)((QKVC * CIN / 4 + 255) / 256), 256>>>(qkv_w, wr, QKVC * CIN);
    round_copy_kernel<<<(int)(((long)DOUT * NHV / 4 + 255) / 256), 256>>>(proj_w, pwr, (long)DOUT * NHV);

    bn_prep_kernel<<<(int)((QKVC + 255) / 256), 256>>>(qkv_gamma, qkv_beta, qkv_mean, qkv_var, qs, qh, (int)QKVC);
    bn_prep_kernel<<<(DOUT + 255) / 256, 256>>>(proj_gamma, proj_beta, proj_mean, proj_var, ps, ph, DOUT);

    const long perB = (long)N_ * QKVC;
    const long NN   = (long)N_ * N_;

    // 1) qkv = round(BN(x @ qkv_w^T))   [16384 x 8192], K=768   (launch #6 -> profiled)
    mma_gemm_kernel<0><<<dim3(QKVC / 128, MTOK / 128, 1), 256, SMEM_BYTES>>>(
        xr, CIN, 0, 0,
        wr, CIN, 0, 0,
        qkv, QKVC, 0, 0,
        CIN, 1, qs, qh, 0.f, 0, 0);

    // 1b) V transpose
    transpose_v_kernel<<<dim3(N_ / 32, VD_ / 32, B_ * H_), dim3(32, 8)>>>(qkv, vt);

    // 2-4) per-batch attention: attn slice (33.5 MB) + pos_bias (33.5 MB) stay L2-resident
    for (int b = 0; b < B_; b++) {
        const float* qb = qkv + (long)b * perB;
        float* attb = attn + (long)b * 8 * NN;

        mma_gemm_kernel<1><<<dim3(N_ / 128, N_ / 128, H_), 256, SMEM_BYTES>>>(
            qb,       QKVC, 0, 1024,
            qb + 256, QKVC, 0, 1024,
            attb, N_, 0, NN,
            KQ_, H_, pos_bias, nullptr, SCALE_, NN, N_);

        softmax1024_kernel<<<(unsigned)(H_ * N_), 128>>>(attb);

        mma_gemm_kernel<2><<<dim3(VD_ / 128, N_ / 128, H_), 256, SMEM_BYTES>>>(
            attb, N_, 0, NN,
            vt + (long)b * 8 * VD_ * N_, N_, 0, (long)VD_ * N_,
            ao + (long)b * N_ * NHV, NHV, 0, VD_,
            N_, H_, nullptr, nullptr, 0.f, 0, 0);
    }

    // 5) out = BN(ao @ proj_w^T)   [16384 x 512], K=4096
    mma_gemm_kernel<3><<<dim3(DOUT / 128, MTOK / 128, 1), 256, SMEM_BYTES>>>(
        ao, NHV, 0, 0,
        pwr, NHV, 0, 0,
        out, DOUT, 0, 0,
        (int)NHV, 1, ps, ph, 0.f, 0, 0);
}

// round 5
// speedup vs baseline: 1.0770x; 1.0770x over previous
#include <cuda_runtime.h>
#include <cstdint>

// ---------------- problem constants ----------------
constexpr int  B_    = 16;
constexpr int  N_    = 1024;
constexpr int  CIN   = 768;
constexpr int  H_    = 8;
constexpr int  KQ_   = 256;
constexpr int  VD_   = 512;
constexpr long MTOK  = 16384;
constexpr long QKVC  = 8192;
constexpr long NHV   = 4096;
constexpr int  DOUT  = 512;
constexpr float SCALE_ = 0.04419417382415922f;     // 512^-0.5
constexpr float EPS_   = 1e-5f;

// ---------------- scratch (device globals) ----------------
__device__ float g_qkv [MTOK * QKVC];                      // 512 MB
__device__ float g_attn[(long)B_ * H_ * N_ * N_];          // 536 MB
__device__ float g_ao  [MTOK * NHV];                       // 268 MB
__device__ float g_vt  [(long)B_ * H_ * VD_ * N_];         // 256 MB
__device__ float g_xr  [MTOK * CIN];                       // 48 MB
__device__ float g_wr  [QKVC * CIN];                       // 25 MB
__device__ float g_pwr [(long)DOUT * NHV];                 // 8 MB
__device__ float g_qs[QKVC], g_qh[QKVC];
__device__ float g_ps[DOUT], g_ph[DOUT];

// ---------------- helpers ----------------
__device__ __forceinline__ float to_tf32(float x) {
    uint32_t u;
    asm("cvt.rna.tf32.f32 %0, %1;" : "=r"(u) : "f"(x));
    return __uint_as_float(u);
}
__device__ __forceinline__ void cp16(uint32_t s, const float* g) {
    asm volatile("cp.async.cg.shared.global [%0], [%1], 16;"
                 :: "r"(s), "l"(__cvta_generic_to_global(g)));
}
__device__ __forceinline__ uint32_t smem_u32(const void* p) {
    uint32_t a;
    asm("{ .reg .u64 t; cvta.to.shared.u64 t, %1; cvt.u32.u64 %0, t; }" : "=r"(a) : "l"(p));
    return a;
}
__device__ __forceinline__ void mma_tf32(float* c, const uint32_t* a, const uint32_t* b) {
    asm volatile(
        "mma.sync.aligned.m16n8k8.row.col.f32.tf32.tf32.f32 "
        "{%0,%1,%2,%3}, {%4,%5,%6,%7}, {%8,%9}, {%0,%1,%2,%3};"
        : "+f"(c[0]), "+f"(c[1]), "+f"(c[2]), "+f"(c[3])
        : "r"(a[0]), "r"(a[1]), "r"(a[2]), "r"(a[3]), "r"(b[0]), "r"(b[1]));
}

// XOR-swizzled smem float index for logical (row, kfloat): 32 floats per row,
// float4-group g = k>>2 is XORed with row&7 -> conflict-free for both cp.async
// stores (8 rows x 8 perm groups) and fragment LDS (8 rows x const-group XOR rg).
__device__ __forceinline__ int swz(int row, int k) {
    return row * 32 + (((k >> 2) ^ (row & 7)) << 2) + (k & 3);
}

// ---------------- mma.sync tf32 GEMM: CTA tile 128x256x32, 2-stage -------------------
// A: [M][K] K-contig (tf32-rounded). B: [N][K] K-contig (tf32-rounded).
// MODE 0: round(BN)   1: alpha*acc + bias   2: round(clamp(-1,1))   3: BN (no round)
constexpr int ACH = 128 * 32;            // floats per A stage (4096)
constexpr int BCH = 256 * 32;            // floats per B stage (8192)
constexpr int SMEM_BYTES = (2 * ACH + 2 * BCH) * 4;   // 98304 B -> 2 CTAs/SM

template<int MODE>
__global__ __launch_bounds__(256)
void mma_gemm_kernel(const float* __restrict__ Aall, long lda, long aos, long ais,
                     const float* __restrict__ Ball, long ldb, long bos, long bis,
                     float* __restrict__ Call, long ldc, long cosz, long cis,
                     int K, int zdiv,
                     const float* __restrict__ p0, const float* __restrict__ p1,
                     float alpha, long bias_is, long ldbias)
{
    extern __shared__ float sm[];        // [A0][A1][B0][B1]
    const uint32_t sbase = smem_u32(sm);

    const int tid = threadIdx.x;
    const int wid = tid >> 5, lane = tid & 31;
    const int wm = wid & 1, wn = wid >> 1;           // 2 x 4 warps; warp tile 64x64
    const int rg = lane >> 2, lg = lane & 3;

    const int z  = blockIdx.z;
    const int zo = z / zdiv, zi = z - zo * zdiv;
    const float* A  = Aall + (long)zo * aos + (long)zi * ais;
    const float* Bp = Ball + (long)zo * bos + (long)zi * bis;
    float*       C  = Call + (long)zo * cosz + (long)zi * cis;
    const long m0 = (long)blockIdx.y * 128;
    const long n0 = (long)blockIdx.x * 256;

    float acc[4][8][4];
#pragma unroll
    for (int i = 0; i < 4; i++)
#pragma unroll
        for (int j = 0; j < 8; j++)
#pragma unroll
            for (int q = 0; q < 4; q++) acc[i][j][q] = 0.f;

    // A stage load: 128 rows x 8 groups = 1024 float4s / 256 thr = 4 iters
    auto loadA = [&](const float* src, long ld, int kc, int stFloatOff) {
        const float* s = src + (long)kc * 32;
#pragma unroll
        for (int i = 0; i < 4; i++) {
            int idx = tid + i * 256;
            int r = idx >> 3, c = idx & 7;
            cp16(sbase + (uint32_t)(stFloatOff + r * 32 + ((c ^ (r & 7)) << 2)) * 4u,
                 s + (long)r * ld + c * 4);
        }
    };
    // B stage load: 256 rows -> 8 iters
    auto loadB = [&](const float* src, long ld, int kc, int stFloatOff) {
        const float* s = src + (long)kc * 32;
#pragma unroll
        for (int i = 0; i < 8; i++) {
            int idx = tid + i * 256;
            int r = idx >> 3, c = idx & 7;
            cp16(sbase + (uint32_t)(stFloatOff + r * 32 + ((c ^ (r & 7)) << 2)) * 4u,
                 s + (long)r * ld + c * 4);
        }
    };

    const float* Abase = A + m0 * lda;
    const float* Bbase = Bp + n0 * ldb;

    const int nch = K >> 5;
    loadA(Abase, lda, 0, 0);
    loadB(Bbase, ldb, 0, 2 * ACH);
    asm volatile("cp.async.commit_group;");

    for (int kc = 0; kc < nch; kc++) {
        const int p = kc & 1;
        if (kc + 1 < nch) {
            loadA(Abase, lda, kc + 1, (p ^ 1) * ACH);
            loadB(Bbase, ldb, kc + 1, 2 * ACH + (p ^ 1) * BCH);
            asm volatile("cp.async.commit_group;");
            asm volatile("cp.async.wait_group 1;");
        } else {
            asm volatile("cp.async.wait_group 0;");
        }
        __syncthreads();

        const float* as = sm + p * ACH;
        const float* bs = sm + 2 * ACH + p * BCH;
        const int arow = wm * 64 + rg;           // row&7 == rg for all frag rows
        const int brow = wn * 64 + rg;
#pragma unroll
        for (int ks = 0; ks < 4; ks++) {
            const int k0 = ks * 8 + lg;          // k for regs 0/1 ; +4 for regs 2/3
            uint32_t a[4][4];
#pragma unroll
            for (int i = 0; i < 4; i++) {
                const int r = arow + i * 16;
                a[i][0] = __float_as_uint(as[swz(r,     k0)]);
                a[i][1] = __float_as_uint(as[swz(r + 8, k0)]);
                a[i][2] = __float_as_uint(as[swz(r,     k0 + 4)]);
                a[i][3] = __float_as_uint(as[swz(r + 8, k0 + 4)]);
            }
#pragma unroll
            for (int j = 0; j < 8; j++) {
                uint32_t b[2];
                const int r = brow + j * 8;
                b[0] = __float_as_uint(bs[swz(r, k0)]);
                b[1] = __float_as_uint(bs[swz(r, k0 + 4)]);
#pragma unroll
                for (int i = 0; i < 4; i++)
                    mma_tf32(acc[i][j], a[i], b);
            }
        }
        __syncthreads();
    }

    // -------- epilogue --------
    const long cr0 = m0 + wm * 64 + rg;
    const long cn0 = n0 + wn * 64 + 2 * lg;
#pragma unroll
    for (int i = 0; i < 4; i++) {
        const long r0 = cr0 + i * 16, r1 = r0 + 8;
#pragma unroll
        for (int j = 0; j < 8; j++) {
            const long cc = cn0 + j * 8;
            float v0 = acc[i][j][0], v1 = acc[i][j][1];
            float v2 = acc[i][j][2], v3 = acc[i][j][3];
            if (MODE == 0 || MODE == 3) {
                const float s0 = p0[cc], s1 = p0[cc + 1];
                const float h0 = p1[cc], h1 = p1[cc + 1];
                v0 = fmaf(v0, s0, h0); v1 = fmaf(v1, s1, h1);
                v2 = fmaf(v2, s0, h0); v3 = fmaf(v3, s1, h1);
                if (MODE == 0) { v0 = to_tf32(v0); v1 = to_tf32(v1); v2 = to_tf32(v2); v3 = to_tf32(v3); }
            } else if (MODE == 1) {
                const float* bias = p0 + (long)zi * bias_is;
                const float2 b0 = *(const float2*)(bias + r0 * ldbias + cc);
                const float2 b1 = *(const float2*)(bias + r1 * ldbias + cc);
                v0 = fmaf(v0, alpha, b0.x); v1 = fmaf(v1, alpha, b0.y);
                v2 = fmaf(v2, alpha, b1.x); v3 = fmaf(v3, alpha, b1.y);
            } else {
                v0 = to_tf32(fminf(fmaxf(v0, -1.f), 1.f));
                v1 = to_tf32(fminf(fmaxf(v1, -1.f), 1.f));
                v2 = to_tf32(fminf(fmaxf(v2, -1.f), 1.f));
                v3 = to_tf32(fminf(fmaxf(v3, -1.f), 1.f));
            }
            *(float2*)(C + r0 * ldc + cc) = make_float2(v0, v1);
            *(float2*)(C + r1 * ldc + cc) = make_float2(v2, v3);
        }
    }
}

// ---------------- small kernels ----------------
__global__ void bn_prep_kernel(const float* __restrict__ g, const float* __restrict__ b,
                               const float* __restrict__ mu, const float* __restrict__ var,
                               float* __restrict__ sc, float* __restrict__ sh, int n) {
    int i = blockIdx.x * blockDim.x + threadIdx.x;
    if (i < n) {
        float s = g[i] * rsqrtf(var[i] + EPS_);
        sc[i] = s;
        sh[i] = b[i] - mu[i] * s;
    }
}

__global__ void round_copy_kernel(const float* __restrict__ in, float* __restrict__ out, long n) {
    long i = ((long)blockIdx.x * blockDim.x + threadIdx.x) * 4;
    if (i < n) {
        float4 v = *(const float4*)(in + i);
        v.x = to_tf32(v.x); v.y = to_tf32(v.y); v.z = to_tf32(v.z); v.w = to_tf32(v.w);
        *(float4*)(out + i) = v;
    }
}

// V transpose: qkv[b,n][h*1024+512+d] -> vt[(b*8+h)*512+d][n]
__global__ void transpose_v_kernel(const float* __restrict__ qkv, float* __restrict__ vt) {
    __shared__ float t[32][33];
    const int z = blockIdx.z, b = z >> 3, h = z & 7;
    const long n0 = (long)blockIdx.x * 32, d0 = (long)blockIdx.y * 32;
    const int tx = threadIdx.x, ty = threadIdx.y;
    const float* src = qkv + (long)b * N_ * QKVC + (long)h * 1024 + 512;
#pragma unroll
    for (int i = 0; i < 32; i += 8)
        t[ty + i][tx] = src[(n0 + ty + i) * QKVC + d0 + tx];
    __syncthreads();
    float* dst = vt + ((long)z * VD_ + d0) * N_ + n0;
#pragma unroll
    for (int i = 0; i < 32; i += 8)
        dst[(ty + i) * (long)N_ + tx] = t[tx][ty + i];
}

// rowwise softmax over 1024, outputs tf32-rounded
__global__ void softmax1024_kernel(float* __restrict__ attn) {
    float* p = attn + (long)blockIdx.x * 1024;
    const int t = threadIdx.x;
    float4 a = ((const float4*)p)[t];
    float4 b = ((const float4*)p)[t + 128];

    float m = fmaxf(fmaxf(fmaxf(a.x, a.y), fmaxf(a.z, a.w)),
                    fmaxf(fmaxf(b.x, b.y), fmaxf(b.z, b.w)));
#pragma unroll
    for (int o = 16; o > 0; o >>= 1) m = fmaxf(m, __shfl_xor_sync(0xffffffffu, m, o));
    __shared__ float sm_[4], ss[4];
    if ((t & 31) == 0) sm_[t >> 5] = m;
    __syncthreads();
    m = fmaxf(fmaxf(sm_[0], sm_[1]), fmaxf(sm_[2], sm_[3]));

    a.x = __expf(a.x - m); a.y = __expf(a.y - m); a.z = __expf(a.z - m); a.w = __expf(a.w - m);
    b.x = __expf(b.x - m); b.y = __expf(b.y - m); b.z = __expf(b.z - m); b.w = __expf(b.w - m);

    float s = a.x + a.y + a.z + a.w + b.x + b.y + b.z + b.w;
#pragma unroll
    for (int o = 16; o > 0; o >>= 1) s += __shfl_xor_sync(0xffffffffu, s, o);
    if ((t & 31) == 0) ss[t >> 5] = s;
    __syncthreads();
    s = ss[0] + ss[1] + ss[2] + ss[3];
    const float inv = 1.0f / s;

    a.x = to_tf32(a.x * inv); a.y = to_tf32(a.y * inv);
    a.z = to_tf32(a.z * inv); a.w = to_tf32(a.w * inv);
    b.x = to_tf32(b.x * inv); b.y = to_tf32(b.y * inv);
    b.z = to_tf32(b.z * inv); b.w = to_tf32(b.w * inv);
    ((float4*)p)[t] = a;
    ((float4*)p)[t + 128] = b;
}

// ---------------- launch ----------------
extern "C" void kernel_launch(void* const* d_in, const int* in_sizes, int n_in,
                              void* d_out, int out_size) {
    const float* x          = (const float*)d_in[0];
    const float* qkv_w      = (const float*)d_in[1];
    const float* qkv_gamma  = (const float*)d_in[2];
    const float* qkv_beta   = (const float*)d_in[3];
    const float* qkv_mean   = (const float*)d_in[4];
    const float* qkv_var    = (const float*)d_in[5];
    const float* pos_bias   = (const float*)d_in[6];
    const float* proj_w     = (const float*)d_in[7];
    const float* proj_gamma = (const float*)d_in[8];
    const float* proj_beta  = (const float*)d_in[9];
    const float* proj_mean  = (const float*)d_in[10];
    const float* proj_var   = (const float*)d_in[11];
    float* out = (float*)d_out;

    float *qkv, *attn, *ao, *vt, *xr, *wr, *pwr, *qs, *qh, *ps, *ph;
    cudaGetSymbolAddress((void**)&qkv,  g_qkv);
    cudaGetSymbolAddress((void**)&attn, g_attn);
    cudaGetSymbolAddress((void**)&ao,   g_ao);
    cudaGetSymbolAddress((void**)&vt,   g_vt);
    cudaGetSymbolAddress((void**)&xr,   g_xr);
    cudaGetSymbolAddress((void**)&wr,   g_wr);
    cudaGetSymbolAddress((void**)&pwr,  g_pwr);
    cudaGetSymbolAddress((void**)&qs,   g_qs);
    cudaGetSymbolAddress((void**)&qh,   g_qh);
    cudaGetSymbolAddress((void**)&ps,   g_ps);
    cudaGetSymbolAddress((void**)&ph,   g_ph);

    cudaFuncSetAttribute(mma_gemm_kernel<0>, cudaFuncAttributeMaxDynamicSharedMemorySize, SMEM_BYTES);
    cudaFuncSetAttribute(mma_gemm_kernel<1>, cudaFuncAttributeMaxDynamicSharedMemorySize, SMEM_BYTES);
    cudaFuncSetAttribute(mma_gemm_kernel<2>, cudaFuncAttributeMaxDynamicSharedMemorySize, SMEM_BYTES);
    cudaFuncSetAttribute(mma_gemm_kernel<3>, cudaFuncAttributeMaxDynamicSharedMemorySize, SMEM_BYTES);

    // tf32-round inputs (first, so launch #6 = QKV GEMM for ncu -s 5 -c 1)
    round_copy_kernel<<<(int)((MTOK * CIN / 4 + 255) / 256), 256>>>(x, xr, MTOK * CIN);
    round_copy_kernel<<<(int)((QKVC * CIN / 4 + 255) / 256), 256>>>(qkv_w, wr, QKVC * CIN);
    round_copy_kernel<<<(int)(((long)DOUT * NHV / 4 + 255) / 256), 256>>>(proj_w, pwr, (long)DOUT * NHV);

    bn_prep_kernel<<<(int)((QKVC + 255) / 256), 256>>>(qkv_gamma, qkv_beta, qkv_mean, qkv_var, qs, qh, (int)QKVC);
    bn_prep_kernel<<<(DOUT + 255) / 256, 256>>>(proj_gamma, proj_beta, proj_mean, proj_var, ps, ph, DOUT);

    const long perB = (long)N_ * QKVC;
    const long NN   = (long)N_ * N_;

    // 1) qkv = round(BN(x @ qkv_w^T))   [16384 x 8192], K=768
    mma_gemm_kernel<0><<<dim3(QKVC / 256, MTOK / 128, 1), 256, SMEM_BYTES>>>(
        xr, CIN, 0, 0,
        wr, CIN, 0, 0,
        qkv, QKVC, 0, 0,
        CIN, 1, qs, qh, 0.f, 0, 0);

    // 1b) V transpose
    transpose_v_kernel<<<dim3(N_ / 32, VD_ / 32, B_ * H_), dim3(32, 8)>>>(qkv, vt);

    // 2) logits = q @ k^T * SCALE + pos_bias[h]   per (b,h): [1024 x 1024], K=256
    mma_gemm_kernel<1><<<dim3(N_ / 256, N_ / 128, B_ * H_), 256, SMEM_BYTES>>>(
        qkv,       QKVC, perB, 1024,
        qkv + 256, QKVC, perB, 1024,
        attn, N_, 8 * NN, NN,
        KQ_, H_, pos_bias, nullptr, SCALE_, NN, N_);

    // 3) softmax
    softmax1024_kernel<<<(unsigned)(B_ * H_ * N_), 128>>>(attn);

    // 4) ao = round(clip(attn @ vt^T)) per (b,h): [1024 x 512], K=1024
    mma_gemm_kernel<2><<<dim3(VD_ / 256, N_ / 128, B_ * H_), 256, SMEM_BYTES>>>(
        attn, N_, 8 * NN, NN,
        vt, N_, 8L * VD_ * N_, (long)VD_ * N_,
        ao, NHV, (long)N_ * NHV, VD_,
        N_, H_, nullptr, nullptr, 0.f, 0, 0);

    // 5) out = BN(ao @ proj_w^T)   [16384 x 512], K=4096
    mma_gemm_kernel<3><<<dim3(DOUT / 256, MTOK / 128, 1), 256, SMEM_BYTES>>>(
        ao, NHV, 0, 0,
        pwr, NHV, 0, 0,
        out, DOUT, 0, 0,
        (int)NHV, 1, ps, ph, 0.f, 0, 0);
}

// round 6
// speedup vs baseline: 1.1116x; 1.0322x over previous
#include <cuda_runtime.h>
#include <cstdint>

// ---------------- problem constants ----------------
constexpr int  B_    = 16;
constexpr int  N_    = 1024;
constexpr int  CIN   = 768;
constexpr int  H_    = 8;
constexpr int  KQ_   = 256;
constexpr int  VD_   = 512;
constexpr long MTOK  = 16384;
constexpr long QKVC  = 8192;
constexpr long NHV   = 4096;
constexpr int  DOUT  = 512;
constexpr float SCALE_ = 0.04419417382415922f;     // 512^-0.5
constexpr float EPS_   = 1e-5f;

// ---------------- scratch (device globals) ----------------
__device__ float g_qkv [MTOK * QKVC];                      // 512 MB
__device__ float g_attn[(long)B_ * H_ * N_ * N_];          // 536 MB
__device__ float g_ao  [MTOK * NHV];                       // 268 MB
__device__ float g_vt  [(long)B_ * H_ * VD_ * N_];         // 256 MB
__device__ float g_xr  [MTOK * CIN];                       // 48 MB
__device__ float g_wr  [QKVC * CIN];                       // 25 MB
__device__ float g_pwr [(long)DOUT * NHV];                 // 8 MB
__device__ float g_qs[QKVC], g_qh[QKVC];
__device__ float g_ps[DOUT], g_ph[DOUT];

// ---------------- helpers ----------------
__device__ __forceinline__ float to_tf32(float x) {
    uint32_t u;
    asm("cvt.rna.tf32.f32 %0, %1;" : "=r"(u) : "f"(x));
    return __uint_as_float(u);
}
__device__ __forceinline__ void cp16(uint32_t s, const float* g) {
    asm volatile("cp.async.cg.shared.global [%0], [%1], 16;"
                 :: "r"(s), "l"(__cvta_generic_to_global(g)));
}
__device__ __forceinline__ uint32_t smem_u32(const void* p) {
    uint32_t a;
    asm("{ .reg .u64 t; cvta.to.shared.u64 t, %1; cvt.u32.u64 %0, t; }" : "=r"(a) : "l"(p));
    return a;
}
__device__ __forceinline__ void mma_tf32(float* c, const uint32_t* a, const uint32_t* b) {
    asm volatile(
        "mma.sync.aligned.m16n8k8.row.col.f32.tf32.tf32.f32 "
        "{%0,%1,%2,%3}, {%4,%5,%6,%7}, {%8,%9}, {%0,%1,%2,%3};"
        : "+f"(c[0]), "+f"(c[1]), "+f"(c[2]), "+f"(c[3])
        : "r"(a[0]), "r"(a[1]), "r"(a[2]), "r"(a[3]), "r"(b[0]), "r"(b[1]));
}

// ---------------- mma.sync tf32 GEMM: tile 128x128x32, 2-stage, occ 2 -----------------
// A: [M][K] K-contig (tf32-rounded). B: [N][K] K-contig (tf32-rounded).
// MODE 0: round(BN)   1: alpha*acc + bias   2: round(clamp(-1,1))   3: BN (no round)
constexpr int LDT = 36;                 // padded smem row (floats) -> conflict-free frags
constexpr int CH  = 128 * LDT;          // floats per tile buffer (4608)
constexpr int SMEM_BYTES = 4 * CH * 4;  // 73728 B -> 2 CTAs/SM

template<int MODE>
__global__ __launch_bounds__(256, 2)
void mma_gemm_kernel(const float* __restrict__ Aall, long lda, long aos, long ais,
                     const float* __restrict__ Ball, long ldb, long bos, long bis,
                     float* __restrict__ Call, long ldc, long cosz, long cis,
                     int K, int zdiv,
                     const float* __restrict__ p0, const float* __restrict__ p1,
                     float alpha, long bias_is, long ldbias)
{
    extern __shared__ float sm[];       // [A0][A1][B0][B1], each CH floats
    const uint32_t sbase = smem_u32(sm);

    const int tid = threadIdx.x;
    const int wid = tid >> 5, lane = tid & 31;
    const int wm = wid & 1, wn = wid >> 1;          // 2 x 4 warp grid
    const int rg = lane >> 2, lg = lane & 3;

    const int z  = blockIdx.z;
    const int zo = z / zdiv, zi = z - zo * zdiv;
    const float* A  = Aall + (long)zo * aos + (long)zi * ais;
    const float* Bp = Ball + (long)zo * bos + (long)zi * bis;
    float*       C  = Call + (long)zo * cosz + (long)zi * cis;
    const long m0 = (long)blockIdx.y * 128;
    const long n0 = (long)blockIdx.x * 128;

    float acc[4][4][4];
#pragma unroll
    for (int i = 0; i < 4; i++)
#pragma unroll
        for (int j = 0; j < 4; j++)
#pragma unroll
            for (int q = 0; q < 4; q++) acc[i][j][q] = 0.f;

    auto load_tile = [&](const float* src, long ld, int kc, int bufFloatOff) {
        const float* s = src + (long)kc * 32;
#pragma unroll
        for (int i = 0; i < 4; i++) {
            int idx = tid + i * 256;             // 0..1023
            int r = idx >> 3, c = idx & 7;       // row 0..127, float4 col 0..7
            cp16(sbase + (uint32_t)(r * LDT + c * 4) * 4u + (uint32_t)bufFloatOff * 4u,
                 s + (long)r * ld + c * 4);
        }
    };

    const float* Abase = A + m0 * lda;
    const float* Bbase = Bp + n0 * ldb;

    const int nch = K >> 5;
    load_tile(Abase, lda, 0, 0);
    load_tile(Bbase, ldb, 0, 2 * CH);
    asm volatile("cp.async.commit_group;");

    for (int kc = 0; kc < nch; kc++) {
        const int p = kc & 1;
        if (kc + 1 < nch) {
            load_tile(Abase, lda, kc + 1, (p ^ 1) * CH);
            load_tile(Bbase, ldb, kc + 1, 2 * CH + (p ^ 1) * CH);
            asm volatile("cp.async.commit_group;");
            asm volatile("cp.async.wait_group 1;");
        } else {
            asm volatile("cp.async.wait_group 0;");
        }
        __syncthreads();

        const float* as = sm + p * CH + (wm * 64 + rg) * LDT + lg;
        const float* bs = sm + 2 * CH + p * CH + (wn * 32 + rg) * LDT + lg;
#pragma unroll
        for (int ks = 0; ks < 4; ks++) {
            uint32_t a[4][4], b[4][2];
#pragma unroll
            for (int i = 0; i < 4; i++) {
                const float* ap = as + i * (16 * LDT) + ks * 8;
                a[i][0] = __float_as_uint(ap[0]);
                a[i][1] = __float_as_uint(ap[8 * LDT]);
                a[i][2] = __float_as_uint(ap[4]);
                a[i][3] = __float_as_uint(ap[8 * LDT + 4]);
            }
#pragma unroll
            for (int j = 0; j < 4; j++) {
                const float* bp = bs + j * (8 * LDT) + ks * 8;
                b[j][0] = __float_as_uint(bp[0]);
                b[j][1] = __float_as_uint(bp[4]);
            }
#pragma unroll
            for (int i = 0; i < 4; i++)
#pragma unroll
                for (int j = 0; j < 4; j++)
                    mma_tf32(acc[i][j], a[i], b[j]);
        }
        __syncthreads();
    }

    // -------- epilogue --------
    const long cr0 = m0 + wm * 64 + rg;
    const long cn0 = n0 + wn * 32 + 2 * lg;
#pragma unroll
    for (int i = 0; i < 4; i++) {
        const long r0 = cr0 + i * 16, r1 = r0 + 8;
#pragma unroll
        for (int j = 0; j < 4; j++) {
            const long cc = cn0 + j * 8;
            float v0 = acc[i][j][0], v1 = acc[i][j][1];
            float v2 = acc[i][j][2], v3 = acc[i][j][3];
            if (MODE == 0 || MODE == 3) {
                const float s0 = p0[cc], s1 = p0[cc + 1];
                const float h0 = p1[cc], h1 = p1[cc + 1];
                v0 = fmaf(v0, s0, h0); v1 = fmaf(v1, s1, h1);
                v2 = fmaf(v2, s0, h0); v3 = fmaf(v3, s1, h1);
                if (MODE == 0) { v0 = to_tf32(v0); v1 = to_tf32(v1); v2 = to_tf32(v2); v3 = to_tf32(v3); }
            } else if (MODE == 1) {
                const float* bias = p0 + (long)zi * bias_is;
                const float2 b0 = *(const float2*)(bias + r0 * ldbias + cc);
                const float2 b1 = *(const float2*)(bias + r1 * ldbias + cc);
                v0 = fmaf(v0, alpha, b0.x); v1 = fmaf(v1, alpha, b0.y);
                v2 = fmaf(v2, alpha, b1.x); v3 = fmaf(v3, alpha, b1.y);
            } else {
                v0 = to_tf32(fminf(fmaxf(v0, -1.f), 1.f));
                v1 = to_tf32(fminf(fmaxf(v1, -1.f), 1.f));
                v2 = to_tf32(fminf(fmaxf(v2, -1.f), 1.f));
                v3 = to_tf32(fminf(fmaxf(v3, -1.f), 1.f));
            }
            *(float2*)(C + r0 * ldc + cc) = make_float2(v0, v1);
            *(float2*)(C + r1 * ldc + cc) = make_float2(v2, v3);
        }
    }
}

// ---------------- small kernels ----------------
__global__ void bn_prep_kernel(const float* __restrict__ g, const float* __restrict__ b,
                               const float* __restrict__ mu, const float* __restrict__ var,
                               float* __restrict__ sc, float* __restrict__ sh, int n) {
    int i = blockIdx.x * blockDim.x + threadIdx.x;
    if (i < n) {
        float s = g[i] * rsqrtf(var[i] + EPS_);
        sc[i] = s;
        sh[i] = b[i] - mu[i] * s;
    }
}

__global__ void round_copy_kernel(const float* __restrict__ in, float* __restrict__ out, long n) {
    long i = ((long)blockIdx.x * blockDim.x + threadIdx.x) * 4;
    if (i < n) {
        float4 v = *(const float4*)(in + i);
        v.x = to_tf32(v.x); v.y = to_tf32(v.y); v.z = to_tf32(v.z); v.w = to_tf32(v.w);
        *(float4*)(out + i) = v;
    }
}

// V transpose: qkv[b,n][h*1024+512+d] -> vt[(b*8+h)*512+d][n]
__global__ void transpose_v_kernel(const float* __restrict__ qkv, float* __restrict__ vt) {
    __shared__ float t[32][33];
    const int z = blockIdx.z, b = z >> 3, h = z & 7;
    const long n0 = (long)blockIdx.x * 32, d0 = (long)blockIdx.y * 32;
    const int tx = threadIdx.x, ty = threadIdx.y;
    const float* src = qkv + (long)b * N_ * QKVC + (long)h * 1024 + 512;
#pragma unroll
    for (int i = 0; i < 32; i += 8)
        t[ty + i][tx] = src[(n0 + ty + i) * QKVC + d0 + tx];
    __syncthreads();
    float* dst = vt + ((long)z * VD_ + d0) * N_ + n0;
#pragma unroll
    for (int i = 0; i < 32; i += 8)
        dst[(ty + i) * (long)N_ + tx] = t[tx][ty + i];
}

// rowwise softmax over 1024, outputs tf32-rounded
__global__ void softmax1024_kernel(float* __restrict__ attn) {
    float* p = attn + (long)blockIdx.x * 1024;
    const int t = threadIdx.x;
    float4 a = ((const float4*)p)[t];
    float4 b = ((const float4*)p)[t + 128];

    float m = fmaxf(fmaxf(fmaxf(a.x, a.y), fmaxf(a.z, a.w)),
                    fmaxf(fmaxf(b.x, b.y), fmaxf(b.z, b.w)));
#pragma unroll
    for (int o = 16; o > 0; o >>= 1) m = fmaxf(m, __shfl_xor_sync(0xffffffffu, m, o));
    __shared__ float sm_[4], ss[4];
    if ((t & 31) == 0) sm_[t >> 5] = m;
    __syncthreads();
    m = fmaxf(fmaxf(sm_[0], sm_[1]), fmaxf(sm_[2], sm_[3]));

    a.x = __expf(a.x - m); a.y = __expf(a.y - m); a.z = __expf(a.z - m); a.w = __expf(a.w - m);
    b.x = __expf(b.x - m); b.y = __expf(b.y - m); b.z = __expf(b.z - m); b.w = __expf(b.w - m);

    float s = a.x + a.y + a.z + a.w + b.x + b.y + b.z + b.w;
#pragma unroll
    for (int o = 16; o > 0; o >>= 1) s += __shfl_xor_sync(0xffffffffu, s, o);
    if ((t & 31) == 0) ss[t >> 5] = s;
    __syncthreads();
    s = ss[0] + ss[1] + ss[2] + ss[3];
    const float inv = 1.0f / s;

    a.x = to_tf32(a.x * inv); a.y = to_tf32(a.y * inv);
    a.z = to_tf32(a.z * inv); a.w = to_tf32(a.w * inv);
    b.x = to_tf32(b.x * inv); b.y = to_tf32(b.y * inv);
    b.z = to_tf32(b.z * inv); b.w = to_tf32(b.w * inv);
    ((float4*)p)[t] = a;
    ((float4*)p)[t + 128] = b;
}

// ---------------- launch ----------------
extern "C" void kernel_launch(void* const* d_in, const int* in_sizes, int n_in,
                              void* d_out, int out_size) {
    const float* x          = (const float*)d_in[0];
    const float* qkv_w      = (const float*)d_in[1];
    const float* qkv_gamma  = (const float*)d_in[2];
    const float* qkv_beta   = (const float*)d_in[3];
    const float* qkv_mean   = (const float*)d_in[4];
    const float* qkv_var    = (const float*)d_in[5];
    const float* pos_bias   = (const float*)d_in[6];
    const float* proj_w     = (const float*)d_in[7];
    const float* proj_gamma = (const float*)d_in[8];
    const float* proj_beta  = (const float*)d_in[9];
    const float* proj_mean  = (const float*)d_in[10];
    const float* proj_var   = (const float*)d_in[11];
    float* out = (float*)d_out;

    float *qkv, *attn, *ao, *vt, *xr, *wr, *pwr, *qs, *qh, *ps, *ph;
    cudaGetSymbolAddress((void**)&qkv,  g_qkv);
    cudaGetSymbolAddress((void**)&attn, g_attn);
    cudaGetSymbolAddress((void**)&ao,   g_ao);
    cudaGetSymbolAddress((void**)&vt,   g_vt);
    cudaGetSymbolAddress((void**)&xr,   g_xr);
    cudaGetSymbolAddress((void**)&wr,   g_wr);
    cudaGetSymbolAddress((void**)&pwr,  g_pwr);
    cudaGetSymbolAddress((void**)&qs,   g_qs);
    cudaGetSymbolAddress((void**)&qh,   g_qh);
    cudaGetSymbolAddress((void**)&ps,   g_ps);
    cudaGetSymbolAddress((void**)&ph,   g_ph);

    cudaFuncSetAttribute(mma_gemm_kernel<0>, cudaFuncAttributeMaxDynamicSharedMemorySize, SMEM_BYTES);
    cudaFuncSetAttribute(mma_gemm_kernel<1>, cudaFuncAttributeMaxDynamicSharedMemorySize, SMEM_BYTES);
    cudaFuncSetAttribute(mma_gemm_kernel<2>, cudaFuncAttributeMaxDynamicSharedMemorySize, SMEM_BYTES);
    cudaFuncSetAttribute(mma_gemm_kernel<3>, cudaFuncAttributeMaxDynamicSharedMemorySize, SMEM_BYTES);

    // launches 1-4 (so launch #5 = QKV GEMM gets profiled by ncu -s 5 -c 1)
    round_copy_kernel<<<(int)((MTOK * CIN / 4 + 255) / 256), 256>>>(x, xr, MTOK * CIN);
    round_copy_kernel<<<(int)((QKVC * CIN / 4 + 255) / 256), 256>>>(qkv_w, wr, QKVC * CIN);
    round_copy_kernel<<<(int)(((long)DOUT * NHV / 4 + 255) / 256), 256>>>(proj_w, pwr, (long)DOUT * NHV);
    bn_prep_kernel<<<(int)((QKVC + 255) / 256), 256>>>(qkv_gamma, qkv_beta, qkv_mean, qkv_var, qs, qh, (int)QKVC);

    const long perB = (long)N_ * QKVC;
    const long NN   = (long)N_ * N_;

    // 1) qkv = round(BN(x @ qkv_w^T))   [16384 x 8192], K=768   -- launch #5, profiled
    mma_gemm_kernel<0><<<dim3(QKVC / 128, MTOK / 128, 1), 256, SMEM_BYTES>>>(
        xr, CIN, 0, 0,
        wr, CIN, 0, 0,
        qkv, QKVC, 0, 0,
        CIN, 1, qs, qh, 0.f, 0, 0);

    bn_prep_kernel<<<(DOUT + 255) / 256, 256>>>(proj_gamma, proj_beta, proj_mean, proj_var, ps, ph, DOUT);

    // 1b) V transpose
    transpose_v_kernel<<<dim3(N_ / 32, VD_ / 32, B_ * H_), dim3(32, 8)>>>(qkv, vt);

    // 2) logits = q @ k^T * SCALE + pos_bias[h]   per (b,h): [1024 x 1024], K=256
    mma_gemm_kernel<1><<<dim3(N_ / 128, N_ / 128, B_ * H_), 256, SMEM_BYTES>>>(
        qkv,       QKVC, perB, 1024,
        qkv + 256, QKVC, perB, 1024,
        attn, N_, 8 * NN, NN,
        KQ_, H_, pos_bias, nullptr, SCALE_, NN, N_);

    // 3) softmax
    softmax1024_kernel<<<(unsigned)(B_ * H_ * N_), 128>>>(attn);

    // 4) ao = round(clip(attn @ vt^T)) per (b,h): [1024 x 512], K=1024
    mma_gemm_kernel<2><<<dim3(VD_ / 128, N_ / 128, B_ * H_), 256, SMEM_BYTES>>>(
        attn, N_, 0 * NN + 8 * NN, NN,
        vt, N_, 8L * VD_ * N_, (long)VD_ * N_,
        ao, NHV, (long)N_ * NHV, VD_,
        N_, H_, nullptr, nullptr, 0.f, 0, 0);

    // 5) out = BN(ao @ proj_w^T)   [16384 x 512], K=4096
    mma_gemm_kernel<3><<<dim3(DOUT / 128, MTOK / 128, 1), 256, SMEM_BYTES>>>(
        ao, NHV, 0, 0,
        pwr, NHV, 0, 0,
        out, DOUT, 0, 0,
        (int)NHV, 1, ps, ph, 0.f, 0, 0);
}

// round 7
// speedup vs baseline: 1.9508x; 1.7550x over previous
#include <cuda_runtime.h>
#include <cuda_fp16.h>
#include <cstdint>

// ---------------- problem constants ----------------
constexpr int  B_    = 16;
constexpr int  N_    = 1024;
constexpr int  CIN   = 768;
constexpr int  H_    = 8;
constexpr int  KQ_   = 256;
constexpr int  VD_   = 512;
constexpr long MTOK  = 16384;
constexpr long QKVC  = 8192;
constexpr long NHV   = 4096;
constexpr int  DOUT  = 512;
constexpr float SCALE_ = 0.04419417382415922f;     // 512^-0.5
constexpr float EPS_   = 1e-5f;

// ---------------- scratch (device globals) ----------------
__device__ __half g_qkvh [MTOK * QKVC];                    // 268 MB
__device__ float  g_attn [(long)B_ * H_ * N_ * N_];        // 536 MB (fp32 logits)
__device__ __half g_attnh[(long)B_ * H_ * N_ * N_];        // 268 MB (probs, half)
__device__ __half g_aoh  [MTOK * NHV];                     // 134 MB
__device__ __half g_vth  [(long)B_ * H_ * VD_ * N_];       // 128 MB
__device__ __half g_xh   [MTOK * CIN];                     // 25 MB
__device__ __half g_wh   [QKVC * CIN];                     // 12.6 MB
__device__ __half g_pwh  [(long)DOUT * NHV];               // 4 MB
__device__ float  g_qs[QKVC], g_qh[QKVC];
__device__ float  g_ps[DOUT], g_ph[DOUT];

// ---------------- helpers ----------------
__device__ __forceinline__ void cp16(uint32_t s, const void* g) {
    asm volatile("cp.async.cg.shared.global [%0], [%1], 16;"
                 :: "r"(s), "l"(__cvta_generic_to_global(g)));
}
__device__ __forceinline__ uint32_t smem_u32(const void* p) {
    uint32_t a;
    asm("{ .reg .u64 t; cvta.to.shared.u64 t, %1; cvt.u32.u64 %0, t; }" : "=r"(a) : "l"(p));
    return a;
}
__device__ __forceinline__ void mma_f16(float* c, const uint32_t* a, const uint32_t* b) {
    asm volatile(
        "mma.sync.aligned.m16n8k16.row.col.f32.f16.f16.f32 "
        "{%0,%1,%2,%3}, {%4,%5,%6,%7}, {%8,%9}, {%0,%1,%2,%3};"
        : "+f"(c[0]), "+f"(c[1]), "+f"(c[2]), "+f"(c[3])
        : "r"(a[0]), "r"(a[1]), "r"(a[2]), "r"(a[3]), "r"(b[0]), "r"(b[1]));
}

// ---------------- fp16 mma GEMM: tile 128x128, K-chunk 64, 2-stage, occ 2 -------------
// A: [M][K] K-contig half. B: [N][K] K-contig half (i.e. C = A * B^T).
// MODE 0: half(BN)   1: fp32 alpha*acc+bias   2: half(clamp(-1,1))   3: fp32 BN
constexpr int LDT = 36;                  // smem row stride in uint32 (=72 halves; 8-half pad)
constexpr int CH  = 128 * LDT;           // uint32 per tile buffer
constexpr int SMEM_BYTES = 4 * CH * 4;   // 73728 B -> 2 CTAs/SM

template<int MODE>
__global__ __launch_bounds__(256, 2)
void hgemm_kernel(const __half* __restrict__ Aall, long lda, long aos, long ais,
                  const __half* __restrict__ Ball, long ldb, long bos, long bis,
                  void* __restrict__ Call, long ldc, long cosz, long cis,
                  int K, int zdiv,
                  const float* __restrict__ p0, const float* __restrict__ p1,
                  float alpha, long bias_is, long ldbias)
{
    extern __shared__ uint32_t smw[];    // [A0][A1][B0][B1], each CH uint32 (half2)
    const uint32_t sbase = smem_u32(smw);

    const int tid = threadIdx.x;
    const int wid = tid >> 5, lane = tid & 31;
    const int wm = wid & 1, wn = wid >> 1;          // 2 x 4 warp grid; warp tile 64x32
    const int rg = lane >> 2, lg = lane & 3;

    const int z  = blockIdx.z;
    const int zo = z / zdiv, zi = z - zo * zdiv;
    const __half* A  = Aall + (long)zo * aos + (long)zi * ais;
    const __half* Bp = Ball + (long)zo * bos + (long)zi * bis;
    const long m0 = (long)blockIdx.y * 128;
    const long n0 = (long)blockIdx.x * 128;

    float acc[4][4][4];
#pragma unroll
    for (int i = 0; i < 4; i++)
#pragma unroll
        for (int j = 0; j < 4; j++)
#pragma unroll
            for (int q = 0; q < 4; q++) acc[i][j][q] = 0.f;

    // one tile = 128 rows x 64 halves (128 B) = 128 x 8 16B-units; 1024 units / 256 thr
    auto load_tile = [&](const __half* src, long ld, int kc, int bufWordOff) {
        const __half* s = src + (long)kc * 64;
#pragma unroll
        for (int i = 0; i < 4; i++) {
            int idx = tid + i * 256;
            int r = idx >> 3, c = idx & 7;           // row, 16B-unit (8 halves)
            cp16(sbase + (uint32_t)(bufWordOff + r * LDT + c * 4) * 4u,
                 s + (long)r * ld + c * 8);
        }
    };

    const __half* Abase = A + m0 * lda;
    const __half* Bbase = Bp + n0 * ldb;

    const int nch = K >> 6;                          // K-chunk 64
    load_tile(Abase, lda, 0, 0);
    load_tile(Bbase, ldb, 0, 2 * CH);
    asm volatile("cp.async.commit_group;");

    for (int kc = 0; kc < nch; kc++) {
        const int p = kc & 1;
        if (kc + 1 < nch) {
            load_tile(Abase, lda, kc + 1, (p ^ 1) * CH);
            load_tile(Bbase, ldb, kc + 1, 2 * CH + (p ^ 1) * CH);
            asm volatile("cp.async.commit_group;");
            asm volatile("cp.async.wait_group 1;");
        } else {
            asm volatile("cp.async.wait_group 0;");
        }
        __syncthreads();

        // half2-word view: row r holds half2 words 0..31 (64 halves), stride LDT
        const uint32_t* as = smw + p * CH + (wm * 64 + rg) * LDT + lg;
        const uint32_t* bs = smw + 2 * CH + p * CH + (wn * 32 + rg) * LDT + lg;
#pragma unroll
        for (int ks = 0; ks < 4; ks++) {             // 4 x k16 steps per 64-chunk
            uint32_t a[4][4], b[4][2];
#pragma unroll
            for (int i = 0; i < 4; i++) {
                const uint32_t* ap = as + i * (16 * LDT) + ks * 8;
                a[i][0] = ap[0];
                a[i][1] = ap[8 * LDT];
                a[i][2] = ap[4];
                a[i][3] = ap[8 * LDT + 4];
            }
#pragma unroll
            for (int j = 0; j < 4; j++) {
                const uint32_t* bp = bs + j * (8 * LDT) + ks * 8;
                b[j][0] = bp[0];
                b[j][1] = bp[4];
            }
#pragma unroll
            for (int i = 0; i < 4; i++)
#pragma unroll
                for (int j = 0; j < 4; j++)
                    mma_f16(acc[i][j], a[i], b[j]);
        }
        __syncthreads();
    }

    // -------- epilogue --------
    const long cr0 = m0 + wm * 64 + rg;
    const long cn0 = n0 + wn * 32 + 2 * lg;
#pragma unroll
    for (int i = 0; i < 4; i++) {
        const long r0 = cr0 + i * 16, r1 = r0 + 8;
#pragma unroll
        for (int j = 0; j < 4; j++) {
            const long cc = cn0 + j * 8;
            float v0 = acc[i][j][0], v1 = acc[i][j][1];
            float v2 = acc[i][j][2], v3 = acc[i][j][3];
            if (MODE == 0 || MODE == 3) {
                const float s0 = p0[cc], s1 = p0[cc + 1];
                const float h0 = p1[cc], h1 = p1[cc + 1];
                v0 = fmaf(v0, s0, h0); v1 = fmaf(v1, s1, h1);
                v2 = fmaf(v2, s0, h0); v3 = fmaf(v3, s1, h1);
            } else if (MODE == 1) {
                const float* bias = p0 + (long)zi * bias_is;
                const float2 b0 = *(const float2*)(bias + r0 * ldbias + cc);
                const float2 b1 = *(const float2*)(bias + r1 * ldbias + cc);
                v0 = fmaf(v0, alpha, b0.x); v1 = fmaf(v1, alpha, b0.y);
                v2 = fmaf(v2, alpha, b1.x); v3 = fmaf(v3, alpha, b1.y);
            } else {
                v0 = fminf(fmaxf(v0, -1.f), 1.f);
                v1 = fminf(fmaxf(v1, -1.f), 1.f);
                v2 = fminf(fmaxf(v2, -1.f), 1.f);
                v3 = fminf(fmaxf(v3, -1.f), 1.f);
            }
            if (MODE == 0 || MODE == 2) {
                __half* Ch = (__half*)Call + (long)zo * cosz + (long)zi * cis;
                *(__half2*)(Ch + r0 * ldc + cc) = __floats2half2_rn(v0, v1);
                *(__half2*)(Ch + r1 * ldc + cc) = __floats2half2_rn(v2, v3);
            } else {
                float* Cf = (float*)Call + (long)zo * cosz + (long)zi * cis;
                *(float2*)(Cf + r0 * ldc + cc) = make_float2(v0, v1);
                *(float2*)(Cf + r1 * ldc + cc) = make_float2(v2, v3);
            }
        }
    }
}

// ---------------- small kernels ----------------
__global__ void bn_prep_kernel(const float* __restrict__ g, const float* __restrict__ b,
                               const float* __restrict__ mu, const float* __restrict__ var,
                               float* __restrict__ sc, float* __restrict__ sh, int n) {
    int i = blockIdx.x * blockDim.x + threadIdx.x;
    if (i < n) {
        float s = g[i] * rsqrtf(var[i] + EPS_);
        sc[i] = s;
        sh[i] = b[i] - mu[i] * s;
    }
}

__global__ void f2h_kernel(const float* __restrict__ in, __half* __restrict__ out, long n) {
    long i = ((long)blockIdx.x * blockDim.x + threadIdx.x) * 8;
    if (i < n) {
        float4 v0 = *(const float4*)(in + i);
        float4 v1 = *(const float4*)(in + i + 4);
        __half2* o = (__half2*)(out + i);
        o[0] = __floats2half2_rn(v0.x, v0.y);
        o[1] = __floats2half2_rn(v0.z, v0.w);
        o[2] = __floats2half2_rn(v1.x, v1.y);
        o[3] = __floats2half2_rn(v1.z, v1.w);
    }
}

// V transpose: qkvh[b,n][h*1024+512+d] -> vth[(b*8+h)*512+d][n]
__global__ void transpose_v_kernel(const __half* __restrict__ qkv, __half* __restrict__ vt) {
    __shared__ __half t[32][33];
    const int z = blockIdx.z, b = z >> 3, h = z & 7;
    const long n0 = (long)blockIdx.x * 32, d0 = (long)blockIdx.y * 32;
    const int tx = threadIdx.x, ty = threadIdx.y;
    const __half* src = qkv + (long)b * N_ * QKVC + (long)h * 1024 + 512;
#pragma unroll
    for (int i = 0; i < 32; i += 8)
        t[ty + i][tx] = src[(n0 + ty + i) * QKVC + d0 + tx];
    __syncthreads();
    __half* dst = vt + ((long)z * VD_ + d0) * N_ + n0;
#pragma unroll
    for (int i = 0; i < 32; i += 8)
        dst[(ty + i) * (long)N_ + tx] = t[tx][ty + i];
}

// rowwise softmax over 1024 fp32 logits -> half probs
__global__ void softmax1024_kernel(const float* __restrict__ attn, __half* __restrict__ attnh) {
    const float* p = attn + (long)blockIdx.x * 1024;
    __half2* ph = (__half2*)(attnh + (long)blockIdx.x * 1024);
    const int t = threadIdx.x;
    float4 a = ((const float4*)p)[t];
    float4 b = ((const float4*)p)[t + 128];

    float m = fmaxf(fmaxf(fmaxf(a.x, a.y), fmaxf(a.z, a.w)),
                    fmaxf(fmaxf(b.x, b.y), fmaxf(b.z, b.w)));
#pragma unroll
    for (int o = 16; o > 0; o >>= 1) m = fmaxf(m, __shfl_xor_sync(0xffffffffu, m, o));
    __shared__ float sm_[4], ss[4];
    if ((t & 31) == 0) sm_[t >> 5] = m;
    __syncthreads();
    m = fmaxf(fmaxf(sm_[0], sm_[1]), fmaxf(sm_[2], sm_[3]));

    a.x = __expf(a.x - m); a.y = __expf(a.y - m); a.z = __expf(a.z - m); a.w = __expf(a.w - m);
    b.x = __expf(b.x - m); b.y = __expf(b.y - m); b.z = __expf(b.z - m); b.w = __expf(b.w - m);

    float s = a.x + a.y + a.z + a.w + b.x + b.y + b.z + b.w;
#pragma unroll
    for (int o = 16; o > 0; o >>= 1) s += __shfl_xor_sync(0xffffffffu, s, o);
    if ((t & 31) == 0) ss[t >> 5] = s;
    __syncthreads();
    s = ss[0] + ss[1] + ss[2] + ss[3];
    const float inv = 1.0f / s;

    ph[2 * t]       = __floats2half2_rn(a.x * inv, a.y * inv);
    ph[2 * t + 1]   = __floats2half2_rn(a.z * inv, a.w * inv);
    ph[256 + 2 * t] = __floats2half2_rn(b.x * inv, b.y * inv);
    ph[257 + 2 * t] = __floats2half2_rn(b.z * inv, b.w * inv);
}

// ---------------- launch ----------------
extern "C" void kernel_launch(void* const* d_in, const int* in_sizes, int n_in,
                              void* d_out, int out_size) {
    const float* x          = (const float*)d_in[0];
    const float* qkv_w      = (const float*)d_in[1];
    const float* qkv_gamma  = (const float*)d_in[2];
    const float* qkv_beta   = (const float*)d_in[3];
    const float* qkv_mean   = (const float*)d_in[4];
    const float* qkv_var    = (const float*)d_in[5];
    const float* pos_bias   = (const float*)d_in[6];
    const float* proj_w     = (const float*)d_in[7];
    const float* proj_gamma = (const float*)d_in[8];
    const float* proj_beta  = (const float*)d_in[9];
    const float* proj_mean  = (const float*)d_in[10];
    const float* proj_var   = (const float*)d_in[11];
    float* out = (float*)d_out;

    __half *qkvh, *attnh, *aoh, *vth, *xh, *wh, *pwh;
    float *attn, *qs, *qh, *ps, *ph;
    cudaGetSymbolAddress((void**)&qkvh,  g_qkvh);
    cudaGetSymbolAddress((void**)&attn,  g_attn);
    cudaGetSymbolAddress((void**)&attnh, g_attnh);
    cudaGetSymbolAddress((void**)&aoh,   g_aoh);
    cudaGetSymbolAddress((void**)&vth,   g_vth);
    cudaGetSymbolAddress((void**)&xh,    g_xh);
    cudaGetSymbolAddress((void**)&wh,    g_wh);
    cudaGetSymbolAddress((void**)&pwh,   g_pwh);
    cudaGetSymbolAddress((void**)&qs,    g_qs);
    cudaGetSymbolAddress((void**)&qh,    g_qh);
    cudaGetSymbolAddress((void**)&ps,    g_ps);
    cudaGetSymbolAddress((void**)&ph,    g_ph);

    cudaFuncSetAttribute(hgemm_kernel<0>, cudaFuncAttributeMaxDynamicSharedMemorySize, SMEM_BYTES);
    cudaFuncSetAttribute(hgemm_kernel<1>, cudaFuncAttributeMaxDynamicSharedMemorySize, SMEM_BYTES);
    cudaFuncSetAttribute(hgemm_kernel<2>, cudaFuncAttributeMaxDynamicSharedMemorySize, SMEM_BYTES);
    cudaFuncSetAttribute(hgemm_kernel<3>, cudaFuncAttributeMaxDynamicSharedMemorySize, SMEM_BYTES);

    // convert inputs to half
    f2h_kernel<<<(int)((MTOK * CIN / 8 + 255) / 256), 256>>>(x, xh, MTOK * CIN);
    f2h_kernel<<<(int)((QKVC * CIN / 8 + 255) / 256), 256>>>(qkv_w, wh, QKVC * CIN);
    f2h_kernel<<<(int)(((long)DOUT * NHV / 8 + 255) / 256), 256>>>(proj_w, pwh, (long)DOUT * NHV);
    bn_prep_kernel<<<(int)((QKVC + 255) / 256), 256>>>(qkv_gamma, qkv_beta, qkv_mean, qkv_var, qs, qh, (int)QKVC);
    bn_prep_kernel<<<(DOUT + 255) / 256, 256>>>(proj_gamma, proj_beta, proj_mean, proj_var, ps, ph, DOUT);

    const long perB = (long)N_ * QKVC;
    const long NN   = (long)N_ * N_;

    // 1) qkvh = half(BN(x @ qkv_w^T))   [16384 x 8192], K=768
    hgemm_kernel<0><<<dim3(QKVC / 128, MTOK / 128, 1), 256, SMEM_BYTES>>>(
        xh, CIN, 0, 0,
        wh, CIN, 0, 0,
        qkvh, QKVC, 0, 0,
        CIN, 1, qs, qh, 0.f, 0, 0);

    // 1b) V transpose (half)
    transpose_v_kernel<<<dim3(N_ / 32, VD_ / 32, B_ * H_), dim3(32, 8)>>>(qkvh, vth);

    // 2) logits(fp32) = q @ k^T * SCALE + pos_bias[h]   per (b,h): [1024 x 1024], K=256
    hgemm_kernel<1><<<dim3(N_ / 128, N_ / 128, B_ * H_), 256, SMEM_BYTES>>>(
        qkvh,       QKVC, perB, 1024,
        qkvh + 256, QKVC, perB, 1024,
        attn, N_, 8 * NN, NN,
        KQ_, H_, pos_bias, nullptr, SCALE_, NN, N_);

    // 3) softmax -> half probs
    softmax1024_kernel<<<(unsigned)(B_ * H_ * N_), 128>>>(attn, attnh);

    // 4) aoh = half(clip(attnh @ vth^T)) per (b,h): [1024 x 512], K=1024
    hgemm_kernel<2><<<dim3(VD_ / 128, N_ / 128, B_ * H_), 256, SMEM_BYTES>>>(
        attnh, N_, 8 * NN, NN,
        vth, N_, 8L * VD_ * N_, (long)VD_ * N_,
        aoh, NHV, (long)N_ * NHV, VD_,
        N_, H_, nullptr, nullptr, 0.f, 0, 0);

    // 5) out = BN(aoh @ proj_w^T)   [16384 x 512], K=4096
    hgemm_kernel<3><<<dim3(DOUT / 128, MTOK / 128, 1), 256, SMEM_BYTES>>>(
        aoh, NHV, 0, 0,
        pwh, NHV, 0, 0,
        out, DOUT, 0, 0,
        (int)NHV, 1, ps, ph, 0.f, 0, 0);
}

// round 8
// speedup vs baseline: 2.0674x; 1.0597x over previous
#include <cuda_runtime.h>
#include <cuda_fp16.h>
#include <cstdint>

// ---------------- problem constants ----------------
constexpr int  B_    = 16;
constexpr int  N_    = 1024;
constexpr int  CIN   = 768;
constexpr int  H_    = 8;
constexpr int  KQ_   = 256;
constexpr int  VD_   = 512;
constexpr long MTOK  = 16384;
constexpr long QKVC  = 8192;
constexpr long NHV   = 4096;
constexpr int  DOUT  = 512;
constexpr float SCALE_ = 0.04419417382415922f;     // 512^-0.5
constexpr float EPS_   = 1e-5f;

// ---------------- scratch (device globals) ----------------
__device__ __half g_qkvh [MTOK * QKVC];
__device__ float  g_attn [(long)B_ * H_ * N_ * N_];
__device__ __half g_attnh[(long)B_ * H_ * N_ * N_];
__device__ __half g_aoh  [MTOK * NHV];
__device__ __half g_vth  [(long)B_ * H_ * VD_ * N_];
__device__ __half g_xh   [MTOK * CIN];
__device__ __half g_wh   [QKVC * CIN];
__device__ __half g_pwh  [(long)DOUT * NHV];
__device__ float  g_qs[QKVC], g_qh[QKVC];
__device__ float  g_ps[DOUT], g_ph[DOUT];

// ---------------- helpers ----------------
__device__ __forceinline__ void cp16(uint32_t s, const void* g) {
    asm volatile("cp.async.cg.shared.global [%0], [%1], 16;"
                 :: "r"(s), "l"(__cvta_generic_to_global(g)));
}
__device__ __forceinline__ uint32_t smem_u32(const void* p) {
    uint32_t a;
    asm("{ .reg .u64 t; cvta.to.shared.u64 t, %1; cvt.u32.u64 %0, t; }" : "=r"(a) : "l"(p));
    return a;
}
__device__ __forceinline__ void mma_f16(float* c, const uint32_t* a, uint32_t b0, uint32_t b1) {
    asm volatile(
        "mma.sync.aligned.m16n8k16.row.col.f32.f16.f16.f32 "
        "{%0,%1,%2,%3}, {%4,%5,%6,%7}, {%8,%9}, {%0,%1,%2,%3};"
        : "+f"(c[0]), "+f"(c[1]), "+f"(c[2]), "+f"(c[3])
        : "r"(a[0]), "r"(a[1]), "r"(a[2]), "r"(a[3]), "r"(b0), "r"(b1));
}
__device__ __forceinline__ void ldsm4(uint32_t* r, uint32_t a) {
    asm volatile("ldmatrix.sync.aligned.m8n8.x4.shared.b16 {%0,%1,%2,%3}, [%4];"
                 : "=r"(r[0]), "=r"(r[1]), "=r"(r[2]), "=r"(r[3]) : "r"(a));
}

// ---------------- fp16 mma GEMM: tile 128x128, K-chunk 64, 3-stage, occ 2 -------------
// A: [M][K] K-contig half. B: [N][K] K-contig half (C = A * B^T).
// MODE 0: half(BN)   1: fp32 alpha*acc+bias   2: half(clamp(-1,1))   3: fp32 BN
constexpr int LDT   = 36;                   // smem row stride in uint32 (72 halves)
constexpr int ROWB  = LDT * 4;              // 144 bytes per row
constexpr int CH    = 128 * LDT;            // uint32 per tile buffer
constexpr int CHB   = CH * 4;               // 18432 bytes per tile buffer
constexpr int NST   = 3;
constexpr int SMEM_BYTES = 2 * NST * CHB;   // 110592 B -> 2 CTAs/SM

template<int MODE>
__global__ __launch_bounds__(256, 2)
void hgemm_kernel(const __half* __restrict__ Aall, long lda, long aos, long ais,
                  const __half* __restrict__ Ball, long ldb, long bos, long bis,
                  void* __restrict__ Call, long ldc, long cosz, long cis,
                  int K, int zdiv,
                  const float* __restrict__ p0, const float* __restrict__ p1,
                  float alpha, long bias_is, long ldbias)
{
    extern __shared__ uint32_t smw[];       // [A0..A2][B0..B2]
    const uint32_t sbase = smem_u32(smw);

    const int tid = threadIdx.x;
    const int wid = tid >> 5, lane = tid & 31;
    const int wm = wid & 1, wn = wid >> 1;            // 2 x 4 warp grid; warp tile 64x32
    const int rg = lane >> 2, lg = lane & 3;

    const int z  = blockIdx.z;
    const int zo = z / zdiv, zi = z - zo * zdiv;
    const __half* A  = Aall + (long)zo * aos + (long)zi * ais;
    const __half* Bp = Ball + (long)zo * bos + (long)zi * bis;
    const long m0 = (long)blockIdx.y * 128;
    const long n0 = (long)blockIdx.x * 128;

    float acc[4][4][4];
#pragma unroll
    for (int i = 0; i < 4; i++)
#pragma unroll
        for (int j = 0; j < 4; j++)
#pragma unroll
            for (int q = 0; q < 4; q++) acc[i][j][q] = 0.f;

    auto load_tile = [&](const __half* src, long ld, int kc, uint32_t bufByteOff) {
        const __half* s = src + (long)kc * 64;
#pragma unroll
        for (int i = 0; i < 4; i++) {
            int idx = tid + i * 256;
            int r = idx >> 3, c = idx & 7;
            cp16(sbase + bufByteOff + (uint32_t)(r * ROWB + c * 16),
                 s + (long)r * ld + c * 8);
        }
    };

    const __half* Abase = A + m0 * lda;
    const __half* Bbase = Bp + n0 * ldb;

    // per-lane ldmatrix base byte offsets (within a stage buffer)
    const uint32_t aOff = (uint32_t)((wm * 64 + (lane & 15)) * ROWB + ((lane >> 4) & 1) * 16);
    const uint32_t bOff = (uint32_t)((wn * 32 + ((lane >> 4) & 1) * 8 + (lane & 7)) * ROWB
                                     + ((lane >> 3) & 1) * 16);

    const int nch = K >> 6;                 // K-chunk 64; nch >= 4 for all GEMMs
    load_tile(Abase, lda, 0, 0);
    load_tile(Bbase, ldb, 0, NST * CHB);
    asm volatile("cp.async.commit_group;");
    load_tile(Abase, lda, 1, CHB);
    load_tile(Bbase, ldb, 1, NST * CHB + CHB);
    asm volatile("cp.async.commit_group;");

    int st = 0;
    for (int kc = 0; kc < nch; kc++) {
        if (kc + 1 < nch) asm volatile("cp.async.wait_group 1;");
        else              asm volatile("cp.async.wait_group 0;");
        __syncthreads();

        if (kc + 2 < nch) {
            int s2 = st + 2; if (s2 >= NST) s2 -= NST;
            load_tile(Abase, lda, kc + 2, (uint32_t)(s2 * CHB));
            load_tile(Bbase, ldb, kc + 2, (uint32_t)(NST * CHB + s2 * CHB));
            asm volatile("cp.async.commit_group;");
        }

        const uint32_t aStage = sbase + st * CHB + aOff;
        const uint32_t bStage = sbase + NST * CHB + st * CHB + bOff;
#pragma unroll
        for (int ks = 0; ks < 4; ks++) {
            uint32_t a[4][4], bfr[2][4];
#pragma unroll
            for (int i = 0; i < 4; i++)
                ldsm4(a[i], aStage + i * (16 * ROWB) + ks * 32);
#pragma unroll
            for (int jj = 0; jj < 2; jj++)
                ldsm4(bfr[jj], bStage + jj * (16 * ROWB) + ks * 32);
#pragma unroll
            for (int i = 0; i < 4; i++)
#pragma unroll
                for (int j = 0; j < 4; j++)
                    mma_f16(acc[i][j], a[i], bfr[j >> 1][(j & 1) * 2], bfr[j >> 1][(j & 1) * 2 + 1]);
        }
        st++; if (st >= NST) st = 0;
    }

    // -------- epilogue --------
    const long cr0 = m0 + wm * 64 + rg;
    const long cn0 = n0 + wn * 32 + 2 * lg;
#pragma unroll
    for (int i = 0; i < 4; i++) {
        const long r0 = cr0 + i * 16, r1 = r0 + 8;
#pragma unroll
        for (int j = 0; j < 4; j++) {
            const long cc = cn0 + j * 8;
            float v0 = acc[i][j][0], v1 = acc[i][j][1];
            float v2 = acc[i][j][2], v3 = acc[i][j][3];
            if (MODE == 0 || MODE == 3) {
                const float s0 = p0[cc], s1 = p0[cc + 1];
                const float h0 = p1[cc], h1 = p1[cc + 1];
                v0 = fmaf(v0, s0, h0); v1 = fmaf(v1, s1, h1);
                v2 = fmaf(v2, s0, h0); v3 = fmaf(v3, s1, h1);
            } else if (MODE == 1) {
                const float* bias = p0 + (long)zi * bias_is;
                const float2 b0 = *(const float2*)(bias + r0 * ldbias + cc);
                const float2 b1 = *(const float2*)(bias + r1 * ldbias + cc);
                v0 = fmaf(v0, alpha, b0.x); v1 = fmaf(v1, alpha, b0.y);
                v2 = fmaf(v2, alpha, b1.x); v3 = fmaf(v3, alpha, b1.y);
            } else {
                v0 = fminf(fmaxf(v0, -1.f), 1.f);
                v1 = fminf(fmaxf(v1, -1.f), 1.f);
                v2 = fminf(fmaxf(v2, -1.f), 1.f);
                v3 = fminf(fmaxf(v3, -1.f), 1.f);
            }
            if (MODE == 0 || MODE == 2) {
                __half* Ch = (__half*)Call + (long)zo * cosz + (long)zi * cis;
                *(__half2*)(Ch + r0 * ldc + cc) = __floats2half2_rn(v0, v1);
                *(__half2*)(Ch + r1 * ldc + cc) = __floats2half2_rn(v2, v3);
            } else {
                float* Cf = (float*)Call + (long)zo * cosz + (long)zi * cis;
                *(float2*)(Cf + r0 * ldc + cc) = make_float2(v0, v1);
                *(float2*)(Cf + r1 * ldc + cc) = make_float2(v2, v3);
            }
        }
    }
}

// ---------------- small kernels ----------------
__global__ void bn_prep_kernel(const float* __restrict__ g, const float* __restrict__ b,
                               const float* __restrict__ mu, const float* __restrict__ var,
                               float* __restrict__ sc, float* __restrict__ sh, int n) {
    int i = blockIdx.x * blockDim.x + threadIdx.x;
    if (i < n) {
        float s = g[i] * rsqrtf(var[i] + EPS_);
        sc[i] = s;
        sh[i] = b[i] - mu[i] * s;
    }
}

__global__ void f2h_kernel(const float* __restrict__ in, __half* __restrict__ out, long n) {
    long i = ((long)blockIdx.x * blockDim.x + threadIdx.x) * 8;
    if (i < n) {
        float4 v0 = *(const float4*)(in + i);
        float4 v1 = *(const float4*)(in + i + 4);
        __half2* o = (__half2*)(out + i);
        o[0] = __floats2half2_rn(v0.x, v0.y);
        o[1] = __floats2half2_rn(v0.z, v0.w);
        o[2] = __floats2half2_rn(v1.x, v1.y);
        o[3] = __floats2half2_rn(v1.z, v1.w);
    }
}

// V transpose: qkvh[b,n][h*1024+512+d] -> vth[(b*8+h)*512+d][n]
__global__ void transpose_v_kernel(const __half* __restrict__ qkv, __half* __restrict__ vt) {
    __shared__ __half t[32][33];
    const int z = blockIdx.z, b = z >> 3, h = z & 7;
    const long n0 = (long)blockIdx.x * 32, d0 = (long)blockIdx.y * 32;
    const int tx = threadIdx.x, ty = threadIdx.y;
    const __half* src = qkv + (long)b * N_ * QKVC + (long)h * 1024 + 512;
#pragma unroll
    for (int i = 0; i < 32; i += 8)
        t[ty + i][tx] = src[(n0 + ty + i) * QKVC + d0 + tx];
    __syncthreads();
    __half* dst = vt + ((long)z * VD_ + d0) * N_ + n0;
#pragma unroll
    for (int i = 0; i < 32; i += 8)
        dst[(ty + i) * (long)N_ + tx] = t[tx][ty + i];
}

// rowwise softmax over 1024 fp32 logits -> half probs
__global__ void softmax1024_kernel(const float* __restrict__ attn, __half* __restrict__ attnh) {
    const float* p = attn + (long)blockIdx.x * 1024;
    __half2* ph = (__half2*)(attnh + (long)blockIdx.x * 1024);
    const int t = threadIdx.x;
    float4 a = ((const float4*)p)[t];
    float4 b = ((const float4*)p)[t + 128];

    float m = fmaxf(fmaxf(fmaxf(a.x, a.y), fmaxf(a.z, a.w)),
                    fmaxf(fmaxf(b.x, b.y), fmaxf(b.z, b.w)));
#pragma unroll
    for (int o = 16; o > 0; o >>= 1) m = fmaxf(m, __shfl_xor_sync(0xffffffffu, m, o));
    __shared__ float sm_[4], ss[4];
    if ((t & 31) == 0) sm_[t >> 5] = m;
    __syncthreads();
    m = fmaxf(fmaxf(sm_[0], sm_[1]), fmaxf(sm_[2], sm_[3]));

    a.x = __expf(a.x - m); a.y = __expf(a.y - m); a.z = __expf(a.z - m); a.w = __expf(a.w - m);
    b.x = __expf(b.x - m); b.y = __expf(b.y - m); b.z = __expf(b.z - m); b.w = __expf(b.w - m);

    float s = a.x + a.y + a.z + a.w + b.x + b.y + b.z + b.w;
#pragma unroll
    for (int o = 16; o > 0; o >>= 1) s += __shfl_xor_sync(0xffffffffu, s, o);
    if ((t & 31) == 0) ss[t >> 5] = s;
    __syncthreads();
    s = ss[0] + ss[1] + ss[2] + ss[3];
    const float inv = 1.0f / s;

    ph[2 * t]       = __floats2half2_rn(a.x * inv, a.y * inv);
    ph[2 * t + 1]   = __floats2half2_rn(a.z * inv, a.w * inv);
    ph[256 + 2 * t] = __floats2half2_rn(b.x * inv, b.y * inv);
    ph[257 + 2 * t] = __floats2half2_rn(b.z * inv, b.w * inv);
}

// ---------------- launch ----------------
extern "C" void kernel_launch(void* const* d_in, const int* in_sizes, int n_in,
                              void* d_out, int out_size) {
    const float* x          = (const float*)d_in[0];
    const float* qkv_w      = (const float*)d_in[1];
    const float* qkv_gamma  = (const float*)d_in[2];
    const float* qkv_beta   = (const float*)d_in[3];
    const float* qkv_mean   = (const float*)d_in[4];
    const float* qkv_var    = (const float*)d_in[5];
    const float* pos_bias   = (const float*)d_in[6];
    const float* proj_w     = (const float*)d_in[7];
    const float* proj_gamma = (const float*)d_in[8];
    const float* proj_beta  = (const float*)d_in[9];
    const float* proj_mean  = (const float*)d_in[10];
    const float* proj_var   = (const float*)d_in[11];
    float* out = (float*)d_out;

    __half *qkvh, *attnh, *aoh, *vth, *xh, *wh, *pwh;
    float *attn, *qs, *qh, *ps, *ph;
    cudaGetSymbolAddress((void**)&qkvh,  g_qkvh);
    cudaGetSymbolAddress((void**)&attn,  g_attn);
    cudaGetSymbolAddress((void**)&attnh, g_attnh);
    cudaGetSymbolAddress((void**)&aoh,   g_aoh);
    cudaGetSymbolAddress((void**)&vth,   g_vth);
    cudaGetSymbolAddress((void**)&xh,    g_xh);
    cudaGetSymbolAddress((void**)&wh,    g_wh);
    cudaGetSymbolAddress((void**)&pwh,   g_pwh);
    cudaGetSymbolAddress((void**)&qs,    g_qs);
    cudaGetSymbolAddress((void**)&qh,    g_qh);
    cudaGetSymbolAddress((void**)&ps,    g_ps);
    cudaGetSymbolAddress((void**)&ph,    g_ph);

    cudaFuncSetAttribute(hgemm_kernel<0>, cudaFuncAttributeMaxDynamicSharedMemorySize, SMEM_BYTES);
    cudaFuncSetAttribute(hgemm_kernel<1>, cudaFuncAttributeMaxDynamicSharedMemorySize, SMEM_BYTES);
    cudaFuncSetAttribute(hgemm_kernel<2>, cudaFuncAttributeMaxDynamicSharedMemorySize, SMEM_BYTES);
    cudaFuncSetAttribute(hgemm_kernel<3>, cudaFuncAttributeMaxDynamicSharedMemorySize, SMEM_BYTES);

    f2h_kernel<<<(int)((MTOK * CIN / 8 + 255) / 256), 256>>>(x, xh, MTOK * CIN);
    f2h_kernel<<<(int)((QKVC * CIN / 8 + 255) / 256), 256>>>(qkv_w, wh, QKVC * CIN);
    f2h_kernel<<<(int)(((long)DOUT * NHV / 8 + 255) / 256), 256>>>(proj_w, pwh, (long)DOUT * NHV);
    bn_prep_kernel<<<(int)((QKVC + 255) / 256), 256>>>(qkv_gamma, qkv_beta, qkv_mean, qkv_var, qs, qh, (int)QKVC);
    bn_prep_kernel<<<(DOUT + 255) / 256, 256>>>(proj_gamma, proj_beta, proj_mean, proj_var, ps, ph, DOUT);

    const long perB = (long)N_ * QKVC;
    const long NN   = (long)N_ * N_;

    // 1) qkvh = half(BN(x @ qkv_w^T))   [16384 x 8192], K=768
    hgemm_kernel<0><<<dim3(QKVC / 128, MTOK / 128, 1), 256, SMEM_BYTES>>>(
        xh, CIN, 0, 0,
        wh, CIN, 0, 0,
        qkvh, QKVC, 0, 0,
        CIN, 1, qs, qh, 0.f, 0, 0);

    // 1b) V transpose (half)
    transpose_v_kernel<<<dim3(N_ / 32, VD_ / 32, B_ * H_), dim3(32, 8)>>>(qkvh, vth);

    // 2) logits(fp32) = q @ k^T * SCALE + pos_bias[h]   per (b,h): [1024 x 1024], K=256
    hgemm_kernel<1><<<dim3(N_ / 128, N_ / 128, B_ * H_), 256, SMEM_BYTES>>>(
        qkvh,       QKVC, perB, 1024,
        qkvh + 256, QKVC, perB, 1024,
        attn, N_, 8 * NN, NN,
        KQ_, H_, pos_bias, nullptr, SCALE_, NN, N_);

    // 3) softmax -> half probs
    softmax1024_kernel<<<(unsigned)(B_ * H_ * N_), 128>>>(attn, attnh);

    // 4) aoh = half(clip(attnh @ vth^T)) per (b,h): [1024 x 512], K=1024
    hgemm_kernel<2><<<dim3(VD_ / 128, N_ / 128, B_ * H_), 256, SMEM_BYTES>>>(
        attnh, N_, 8 * NN, NN,
        vth, N_, 8L * VD_ * N_, (long)VD_ * N_,
        aoh, NHV, (long)N_ * NHV, VD_,
        N_, H_, nullptr, nullptr, 0.f, 0, 0);

    // 5) out = BN(aoh @ proj_w^T)   [16384 x 512], K=4096
    hgemm_kernel<3><<<dim3(DOUT / 128, MTOK / 128, 1), 256, SMEM_BYTES>>>(
        aoh, NHV, 0, 0,
        pwh, NHV, 0, 0,
        out, DOUT, 0, 0,
        (int)NHV, 1, ps, ph, 0.f, 0, 0);
}